// round 5
// baseline (speedup 1.0000x reference)
#include <cuda_runtime.h>

// BiasedFeatureDropout: out = x * 1.25 * (threefry_bits(i) < T(channel))
// Bit-exact JAX partitionable threefry-2x32, keys (0,1), counter hi=0.
//
// Round-5 build (= round-4 candidate, re-bench after infra failure):
//  - rot16/rot24 rounds (4 of 20) via PRMT (1 alu cyc vs SHF's 2)
//  - 13 rounds via IMAD.WIDE rotate (fma) + fused LOP3 (lo|hi)^c (alu)
//  - 3 rounds keep SHF
//  - every add forced onto IMAD (fma pipe) via mad.lo.u32 with opaque 'one'
//  Target: fma-cycles ~= alu-cycles ~= 39/elem -> SMSP alternates pipes.

static constexpr unsigned KS2      = 0x1BD11BDBu;   // 0 ^ 1 ^ 0x1BD11BDA
static constexpr unsigned HW       = 56u * 56u;     // 3136, divisible by 8
static constexpr unsigned THR_BIAS = 858993664u;    // keep=0.2f
static constexpr unsigned THR_REG  = 3435974144u;   // keep=0.8f

// a*one + c -> IMAD (fma pipe); 'one' is a runtime kernel arg (==1)
__device__ __forceinline__ unsigned madd(unsigned a, unsigned one, unsigned c) {
    unsigned r;
    asm("mad.lo.u32 %0, %1, %2, %3;" : "=r"(r) : "r"(a), "r"(one), "r"(c));
    return r;
}

struct Pows { unsigned p6, p13, p15, p17, p26, p29; };

// wide round: IMAD add (fma) + IMAD.WIDE rotate (fma) + LOP3 (lo|hi)^x0 (alu)
#define RW(pp)      { x0 = madd(x1, one, x0);                                \
                      unsigned long long t = (unsigned long long)x1 * (pp);  \
                      x1 = ((unsigned)t | (unsigned)(t >> 32)) ^ x0; }
// wide round with folded x0 injection (IADD3, alu)
#define RWF(pp, a)  { x0 = x0 + x1 + (a);                                    \
                      unsigned long long t = (unsigned long long)x1 * (pp);  \
                      x1 = ((unsigned)t | (unsigned)(t >> 32)) ^ x0; }
// PRMT round: rot16 sel=0x1032, rot24 sel=0x0321 (1 alu cyc rotate)
#define RP(sel)     { x0 = madd(x1, one, x0);                                \
                      x1 = __byte_perm(x1, 0u, (sel)) ^ x0; }
// classic SHF round
#define RS(rr)      { x0 = madd(x1, one, x0);                                \
                      x1 = __funnelshift_l(x1, x1, (rr)) ^ x0; }
// SHF round with folded x0 injection
#define RSF(rr, a)  { x0 = x0 + x1 + (a);                                    \
                      x1 = __funnelshift_l(x1, x1, (rr)) ^ x0; }

__device__ __forceinline__ unsigned threefry_bits(unsigned ctr, unsigned one,
                                                  const Pows& P) {
    unsigned x0, x1;
    x1 = madd(ctr, one, 1u);                     // x1 = ctr + ks1(=1)
    // r1 (rot13): x0 = 0 + x1; x1 = rot13(x1) ^ x0   [wide]
    x0 = x1;
    {   unsigned long long t = (unsigned long long)x1 * P.p13;
        x1 = ((unsigned)t | (unsigned)(t >> 32)) ^ x0; }
    RW(P.p15) RW(P.p26) RW(P.p6)                 // r2-r4
    x1 = madd(x1, one, KS2 + 1u);                // inj1: x1 += ks2+1
    RWF(P.p17, 1u)                               // r5  (x0 += ks1=1 folded)
    RW(P.p29)                                    // r6
    RP(0x1032u)                                  // r7  rot16
    RP(0x0321u)                                  // r8  rot24
    x1 = madd(x1, one, 2u);                      // inj2: x1 += ks0+2
    RSF(13, KS2)                                 // r9  (x0 += ks2 folded)
    RW(P.p15) RW(P.p26) RW(P.p6)                 // r10-r12
    x1 = madd(x1, one, 4u);                      // inj3: x1 += ks1+3
    RS(17)                                       // r13 (x0 += ks0=0, free)
    RW(P.p29)                                    // r14
    RP(0x1032u)                                  // r15 rot16
    RP(0x0321u)                                  // r16 rot24
    x1 = madd(x1, one, KS2 + 4u);                // inj4: x1 += ks2+4
    RSF(13, 1u)                                  // r17 (x0 += ks1=1 folded)
    RW(P.p15) RW(P.p26) RW(P.p6)                 // r18-r20
    // final: (x0 + ks2) ^ (x1 + ks0 + 5)
    return (x0 + KS2) ^ madd(x1, one, 5u);
}

__global__ __launch_bounds__(256)
void biased_dropout_kernel(const float4* __restrict__ x,
                           float4* __restrict__ y,
                           unsigned one,            // always 1, opaque to ptxas
                           unsigned n_thr) {
    unsigned t = blockIdx.x * blockDim.x + threadIdx.x;
    if (t >= n_thr) return;

    unsigned base = t * 8u;
    unsigned ch  = (base / HW) & 255u;               // HW % 8 == 0
    unsigned thr = (ch < 32u) ? THR_BIAS : THR_REG;

    Pows P;
    P.p6  = one << 6;  P.p13 = one << 13; P.p15 = one << 15;
    P.p17 = one << 17; P.p26 = one << 26; P.p29 = one << 29;

    float4 v0 = x[2u * t];
    float4 v1 = x[2u * t + 1u];

    unsigned b[8];
#pragma unroll
    for (int i = 0; i < 8; i++)
        b[i] = threefry_bits(base + (unsigned)i, one, P);

    float4 o0, o1;
    o0.x = (b[0] < thr) ? v0.x * 1.25f : 0.0f;
    o0.y = (b[1] < thr) ? v0.y * 1.25f : 0.0f;
    o0.z = (b[2] < thr) ? v0.z * 1.25f : 0.0f;
    o0.w = (b[3] < thr) ? v0.w * 1.25f : 0.0f;
    o1.x = (b[4] < thr) ? v1.x * 1.25f : 0.0f;
    o1.y = (b[5] < thr) ? v1.y * 1.25f : 0.0f;
    o1.z = (b[6] < thr) ? v1.z * 1.25f : 0.0f;
    o1.w = (b[7] < thr) ? v1.w * 1.25f : 0.0f;

    y[2u * t]      = o0;
    y[2u * t + 1u] = o1;
}

extern "C" void kernel_launch(void* const* d_in, const int* in_sizes, int n_in,
                              void* d_out, int out_size) {
    (void)n_in; (void)out_size;
    const float4* x = (const float4*)d_in[0];
    float4* y = (float4*)d_out;
    unsigned n = (unsigned)in_sizes[0];          // 51,380,224
    unsigned n_thr = n / 8u;                     // 6,422,528 (exact)
    unsigned blocks = (n_thr + 255u) / 256u;     // 25,088
    biased_dropout_kernel<<<blocks, 256>>>(x, y, 1u, n_thr);
}

// round 6
// speedup vs baseline: 1.1041x; 1.1041x over previous
#include <cuda_runtime.h>

// BiasedFeatureDropout: out = x * 1.25 * (threefry_bits(i) < T(channel))
// Bit-exact JAX partitionable threefry-2x32, keys (0,1), counter hi=0.
//
// Round-6 build: R1 structure (SHF/LOP3 rounds, 4 elems/thread) but with
//  - ALL adds steered to the fma pipe as IMAD via runtime-opaque 'one'
//  - rot16/rot24 rounds via PRMT (alu, 1 slot) instead of SHF
//  - NO IMAD.WIDE rotates (hidden ~2-cycle fma cost killed R2/R3/R5)
// Target: alu ~46 slots/elem (binding) vs R1's ~64.

static constexpr unsigned KS2      = 0x1BD11BDBu;   // 0 ^ 1 ^ 0x1BD11BDA
static constexpr unsigned HW       = 56u * 56u;     // 3136, divisible by 4
static constexpr unsigned THR_BIAS = 858993664u;    // keep=0.2f
static constexpr unsigned THR_REG  = 3435974144u;   // keep=0.8f

// a*one + c -> IMAD (fma pipe); 'one' is a runtime kernel arg (==1)
__device__ __forceinline__ unsigned madd(unsigned a, unsigned one, unsigned c) {
    unsigned r;
    asm("mad.lo.u32 %0, %1, %2, %3;" : "=r"(r) : "r"(a), "r"(one), "r"(c));
    return r;
}

// SHF round: IMAD add (fma) + SHF rotate (alu) + LOP3 xor (alu)
#define RS(rr)      { x0 = madd(x1, one, x0);                     \
                      x1 = __funnelshift_l(x1, x1, (rr)) ^ x0; }
// SHF round with folded x0 key-injection (IADD3, alu)
#define RSF(rr, a)  { x0 = x0 + x1 + (a);                         \
                      x1 = __funnelshift_l(x1, x1, (rr)) ^ x0; }
// PRMT round: rot16 sel=0x1032, rot24 sel=0x0321 (PRMT alu 1 slot + LOP3)
#define RP(sel)     { x0 = madd(x1, one, x0);                     \
                      x1 = __byte_perm(x1, 0u, (sel)) ^ x0; }

__device__ __forceinline__ unsigned threefry_bits(unsigned ctr, unsigned one) {
    unsigned x0, x1;
    x1 = madd(ctr, one, 1u);                     // x1 = ctr + ks1(=1)
    // r1 (rot13): x0 = 0 + x1 (free), x1 = rot13(x1) ^ x0
    x0 = x1;
    x1 = __funnelshift_l(x1, x1, 13) ^ x0;
    RS(15) RS(26) RS(6)                          // r2-r4
    x1 = madd(x1, one, KS2 + 1u);                // inj1: x1 += ks2+1
    RSF(17, 1u)                                  // r5  (x0 += ks1=1 folded)
    RS(29)                                       // r6
    RP(0x1032u)                                  // r7  rot16
    RP(0x0321u)                                  // r8  rot24
    x1 = madd(x1, one, 2u);                      // inj2: x1 += ks0+2
    RSF(13, KS2)                                 // r9  (x0 += ks2 folded)
    RS(15) RS(26) RS(6)                          // r10-r12
    x1 = madd(x1, one, 4u);                      // inj3: x1 += ks1+3
    RS(17)                                       // r13 (x0 += ks0=0, free)
    RS(29)                                       // r14
    RP(0x1032u)                                  // r15 rot16
    RP(0x0321u)                                  // r16 rot24
    x1 = madd(x1, one, KS2 + 4u);                // inj4: x1 += ks2+4
    RSF(13, 1u)                                  // r17 (x0 += ks1=1 folded)
    RS(15) RS(26) RS(6)                          // r18-r20
    // final: (x0 + ks2) ^ (x1 + ks0 + 5)
    return (x0 + KS2) ^ madd(x1, one, 5u);
}

__global__ __launch_bounds__(256)
void biased_dropout_kernel(const float4* __restrict__ x,
                           float4* __restrict__ y,
                           unsigned one,            // always 1, opaque to ptxas
                           unsigned n_vec) {
    unsigned t = blockIdx.x * blockDim.x + threadIdx.x;
    if (t >= n_vec) return;

    unsigned base = t * 4u;
    unsigned ch  = (base / HW) & 255u;               // HW % 4 == 0
    unsigned thr = (ch < 32u) ? THR_BIAS : THR_REG;

    float4 v = x[t];

    unsigned b0 = threefry_bits(base + 0u, one);
    unsigned b1 = threefry_bits(base + 1u, one);
    unsigned b2 = threefry_bits(base + 2u, one);
    unsigned b3 = threefry_bits(base + 3u, one);

    float4 o;
    o.x = (b0 < thr) ? v.x * 1.25f : 0.0f;
    o.y = (b1 < thr) ? v.y * 1.25f : 0.0f;
    o.z = (b2 < thr) ? v.z * 1.25f : 0.0f;
    o.w = (b3 < thr) ? v.w * 1.25f : 0.0f;

    y[t] = o;
}

extern "C" void kernel_launch(void* const* d_in, const int* in_sizes, int n_in,
                              void* d_out, int out_size) {
    (void)n_in; (void)out_size;
    const float4* x = (const float4*)d_in[0];
    float4* y = (float4*)d_out;
    unsigned n = (unsigned)in_sizes[0];          // 51,380,224
    unsigned n_vec = n / 4u;                     // 12,845,056 (exact)
    unsigned blocks = (n_vec + 255u) / 256u;     // 50,176
    biased_dropout_kernel<<<blocks, 256>>>(x, y, 1u, n_vec);
}